// round 3
// baseline (speedup 1.0000x reference)
#include <cuda_runtime.h>
#include <cuda_bf16.h>
#include <mma.h>
#include <cstdint>

using namespace nvcuda;

// Problem constants
#define CUR    1024
#define FULL   2048
#define BSZ    4
#define DMODEL 1024
#define HN     16
#define HD     64
#define PREV   (FULL - CUR)      // 1024
#define ZB     (BSZ * HN)        // 64 batched heads
#define SCALE  0.125f            // 1/sqrt(64)

#define IT 64                    // flash i-tile
#define JT 128                   // flash j-tile
#define RW 192                   // r-window (JT + IT - 1 rounded)

// ---------------------------------------------------------------------------
// Scratch
// ---------------------------------------------------------------------------
__device__ float g_kv [ (size_t)FULL * BSZ * 2 * HN * HD ];   // 8192 x 2048
__device__ float g_q  [ (size_t)CUR * BSZ * HN * HD ];        // 4096 x 1024
__device__ float g_qu [ (size_t)CUR * BSZ * HN * HD ];
__device__ float g_qv [ (size_t)CUR * BSZ * HN * HD ];
__device__ float g_r  [ (size_t)FULL * HN * HD ];             // 2048 x 1024
__device__ float g_ctx[ (size_t)CUR * BSZ * HN * HD ];
__device__ float g_beff[ DMODEL ];

// ---------------------------------------------------------------------------
// Generic TF32 GEMM: C[M,N] = A[M,K] @ B[K,N]  (unchanged from R2)
// ---------------------------------------------------------------------------
__global__ __launch_bounds__(256) void gemm_tf32(
    const float* __restrict__ A, const float* __restrict__ B,
    float* __restrict__ C, int M, int N, int K)
{
    __shared__ float sA[128][40];
    __shared__ float sB[32][136];
    int tid = threadIdx.x, warp = tid >> 5;
    int wm = warp >> 2, wn = warp & 3;
    int m0 = blockIdx.y * 128, n0 = blockIdx.x * 128;

    wmma::fragment<wmma::accumulator, 16, 16, 8, float> acc[4][2];
#pragma unroll
    for (int i = 0; i < 4; i++)
#pragma unroll
        for (int j = 0; j < 2; j++) wmma::fill_fragment(acc[i][j], 0.f);

    int am = tid >> 1,  ak = (tid & 1) * 16;
    int bk = tid >> 3,  bn = (tid & 7) * 16;

    for (int k0 = 0; k0 < K; k0 += 32) {
        const float* ap = A + (size_t)(m0 + am) * K + k0 + ak;
#pragma unroll
        for (int s = 0; s < 4; s++) {
            float4 v = *reinterpret_cast<const float4*>(ap + 4 * s);
            sA[am][ak + 4 * s + 0] = wmma::__float_to_tf32(v.x);
            sA[am][ak + 4 * s + 1] = wmma::__float_to_tf32(v.y);
            sA[am][ak + 4 * s + 2] = wmma::__float_to_tf32(v.z);
            sA[am][ak + 4 * s + 3] = wmma::__float_to_tf32(v.w);
        }
        const float* bp = B + (size_t)(k0 + bk) * N + n0 + bn;
#pragma unroll
        for (int s = 0; s < 4; s++) {
            float4 v = *reinterpret_cast<const float4*>(bp + 4 * s);
            sB[bk][bn + 4 * s + 0] = wmma::__float_to_tf32(v.x);
            sB[bk][bn + 4 * s + 1] = wmma::__float_to_tf32(v.y);
            sB[bk][bn + 4 * s + 2] = wmma::__float_to_tf32(v.z);
            sB[bk][bn + 4 * s + 3] = wmma::__float_to_tf32(v.w);
        }
        __syncthreads();
#pragma unroll
        for (int kk = 0; kk < 4; kk++) {
            wmma::fragment<wmma::matrix_a, 16, 16, 8, wmma::precision::tf32, wmma::row_major> af[4];
            wmma::fragment<wmma::matrix_b, 16, 16, 8, wmma::precision::tf32, wmma::row_major> bf[2];
#pragma unroll
            for (int i = 0; i < 4; i++)
                wmma::load_matrix_sync(af[i], &sA[wm * 64 + i * 16][kk * 8], 40);
#pragma unroll
            for (int j = 0; j < 2; j++)
                wmma::load_matrix_sync(bf[j], &sB[kk * 8][wn * 32 + j * 16], 136);
#pragma unroll
            for (int i = 0; i < 4; i++)
#pragma unroll
                for (int j = 0; j < 2; j++)
                    wmma::mma_sync(acc[i][j], af[i], bf[j], acc[i][j]);
        }
        __syncthreads();
    }
#pragma unroll
    for (int i = 0; i < 4; i++)
#pragma unroll
        for (int j = 0; j < 2; j++)
            wmma::store_matrix_sync(
                C + (size_t)(m0 + wm * 64 + i * 16) * N + n0 + wn * 32 + j * 16,
                acc[i][j], N, wmma::mem_row_major);
}

// ---------------------------------------------------------------------------
// qu = q + (b_q + u)[n],  qv = q + (b_q + v)[n]
// ---------------------------------------------------------------------------
__global__ __launch_bounds__(256) void quv_kernel(
    const float* __restrict__ q, const float* __restrict__ b_q,
    const float* __restrict__ u, const float* __restrict__ v,
    float* __restrict__ qu, float* __restrict__ qv)
{
    int idx = blockIdx.x * 256 + threadIdx.x;
    int n4 = idx & 255;
    float4 qq = reinterpret_cast<const float4*>(q)[idx];
    float4 bb = reinterpret_cast<const float4*>(b_q)[n4];
    float4 uu = reinterpret_cast<const float4*>(u)[n4];
    float4 vv = reinterpret_cast<const float4*>(v)[n4];
    float4 a, c;
    a.x = qq.x + bb.x + uu.x; a.y = qq.y + bb.y + uu.y;
    a.z = qq.z + bb.z + uu.z; a.w = qq.w + bb.w + uu.w;
    c.x = qq.x + bb.x + vv.x; c.y = qq.y + bb.y + vv.y;
    c.z = qq.z + bb.z + vv.z; c.w = qq.w + bb.w + vv.w;
    reinterpret_cast<float4*>(qu)[idx] = a;
    reinterpret_cast<float4*>(qv)[idx] = c;
}

__global__ __launch_bounds__(256) void beff_kernel(
    const float* __restrict__ b_kv, const float* __restrict__ W_proj,
    const float* __restrict__ b_proj, float* __restrict__ beff)
{
    int n = blockIdx.x * 256 + threadIdx.x;
    float acc = b_proj[n];
    for (int m = 0; m < DMODEL; m++)
        acc += b_kv[DMODEL + m] * W_proj[(size_t)m * DMODEL + n];
    beff[n] = acc;
}

__global__ __launch_bounds__(256) void bias_add_kernel(
    float* __restrict__ out, const float* __restrict__ beff)
{
    int idx = blockIdx.x * 256 + threadIdx.x;
    int n4 = idx & 255;
    float4 o = reinterpret_cast<float4*>(out)[idx];
    float4 b = reinterpret_cast<const float4*>(beff)[n4];
    o.x += b.x; o.y += b.y; o.z += b.z; o.w += b.w;
    reinterpret_cast<float4*>(out)[idx] = o;
}

// ---------------------------------------------------------------------------
// Flash attention with exact rel_shift:
// one block per (i-tile of 64, z). Loops j-tiles of 128; never materializes
// the score matrices. Position term via 192-wide r-window GEMM + smem gather:
//   pos[i,j] = qv_i . r[j + 1023 - i]   (t = tbase + (jl + 63 - il), tbase = j0+960-i0)
// Online softmax state (m, l, alpha) and O accumulator live in smem.
// ---------------------------------------------------------------------------
// smem float offsets
#define OFF_QU 0           // 64 x 68
#define OFF_QV 4352        // 64 x 68
#define OFF_K  8704        // 128 x 68  (K tile, later aliased by V tile)
#define OFF_R  17408       // 192 x 68
#define OFF_C  30464       // 64 x 132  (content scores, later tf32 probs)
#define OFF_P2 38912       // 64 x 196  (pos window scores, later PV partial 64x68)
#define OFF_O  51456       // 64 x 68
#define OFF_M  55808
#define OFF_L  55872
#define OFF_AL 55936
#define SMEM_FLOATS 56000  // 224000 bytes

__global__ __launch_bounds__(256) void flash_kernel(
    const float* __restrict__ qu, const float* __restrict__ qv,
    const float* __restrict__ kv, const float* __restrict__ r,
    float* __restrict__ ctx)
{
    extern __shared__ float sm[];
    float* sQU = sm + OFF_QU;
    float* sQV = sm + OFF_QV;
    float* sK  = sm + OFF_K;
    float* sR  = sm + OFF_R;
    float* sC  = sm + OFF_C;
    float* sP2 = sm + OFF_P2;
    float* sO  = sm + OFF_O;
    float* sM  = sm + OFF_M;
    float* sL  = sm + OFF_L;
    float* sAl = sm + OFF_AL;

    int tid = threadIdx.x, warp = tid >> 5;
    int i0 = blockIdx.x * IT;
    int z  = blockIdx.y;
    int b  = z >> 4, h = z & 15;

    const float* A0  = qu + b * DMODEL + h * HD;     // stride 4096
    const float* Av0 = qv + b * DMODEL + h * HD;     // stride 4096
    const float* K0  = kv + (size_t)b * 2048 + h * HD;       // stride 8192
    const float* V0  = K0 + DMODEL;                           // stride 8192
    const float* R0  = r + h * HD;                            // stride 1024

    // Load QU/QV tiles (64 x 64), init O/M/L
    {
        int ri = tid >> 2, c0 = (tid & 3) * 16;
        const float* pu = A0  + (size_t)(i0 + ri) * (BSZ * DMODEL) + c0;
        const float* pv = Av0 + (size_t)(i0 + ri) * (BSZ * DMODEL) + c0;
#pragma unroll
        for (int s = 0; s < 4; s++) {
            float4 a = *reinterpret_cast<const float4*>(pu + 4 * s);
            sQU[ri * 68 + c0 + 4 * s + 0] = wmma::__float_to_tf32(a.x);
            sQU[ri * 68 + c0 + 4 * s + 1] = wmma::__float_to_tf32(a.y);
            sQU[ri * 68 + c0 + 4 * s + 2] = wmma::__float_to_tf32(a.z);
            sQU[ri * 68 + c0 + 4 * s + 3] = wmma::__float_to_tf32(a.w);
            float4 c = *reinterpret_cast<const float4*>(pv + 4 * s);
            sQV[ri * 68 + c0 + 4 * s + 0] = wmma::__float_to_tf32(c.x);
            sQV[ri * 68 + c0 + 4 * s + 1] = wmma::__float_to_tf32(c.y);
            sQV[ri * 68 + c0 + 4 * s + 2] = wmma::__float_to_tf32(c.z);
            sQV[ri * 68 + c0 + 4 * s + 3] = wmma::__float_to_tf32(c.w);
        }
#pragma unroll
        for (int k = 0; k < 16; k++) sO[ri * 68 + c0 + k] = 0.f;
        if (tid < 64) { sM[tid] = -1e30f; sL[tid] = 0.f; }
    }
    __syncthreads();

    int njt = (i0 + IT + PREV + JT - 1) >> 7;   // ceil((i0+1088)/128)

    for (int jt = 0; jt < njt; jt++) {
        int j0 = jt * JT;

        // ---- load K tile (128 x 64) ----
        {
            int row = tid >> 1, c0 = (tid & 1) * 32;
            const float* p = K0 + (size_t)(j0 + row) * (BSZ * 2 * DMODEL) + c0;
#pragma unroll
            for (int s = 0; s < 8; s++) {
                float4 v = *reinterpret_cast<const float4*>(p + 4 * s);
                sK[row * 68 + c0 + 4 * s + 0] = wmma::__float_to_tf32(v.x);
                sK[row * 68 + c0 + 4 * s + 1] = wmma::__float_to_tf32(v.y);
                sK[row * 68 + c0 + 4 * s + 2] = wmma::__float_to_tf32(v.z);
                sK[row * 68 + c0 + 4 * s + 3] = wmma::__float_to_tf32(v.w);
            }
        }
        // ---- load R window (192 x 64) ----
        {
            int tbase = j0 + 960 - i0;
            for (int idx = tid; idx < RW * 2; idx += 256) {
                int row = idx >> 1, c0 = (idx & 1) * 32;
                int t = tbase + row; if (t > FULL - 1) t = FULL - 1;   // clamped rows are masked later
                const float* p = R0 + (size_t)t * (HN * HD) + c0;
#pragma unroll
                for (int s = 0; s < 8; s++) {
                    float4 v = *reinterpret_cast<const float4*>(p + 4 * s);
                    sR[row * 68 + c0 + 4 * s + 0] = wmma::__float_to_tf32(v.x);
                    sR[row * 68 + c0 + 4 * s + 1] = wmma::__float_to_tf32(v.y);
                    sR[row * 68 + c0 + 4 * s + 2] = wmma::__float_to_tf32(v.z);
                    sR[row * 68 + c0 + 4 * s + 3] = wmma::__float_to_tf32(v.w);
                }
            }
        }
        __syncthreads();

        // ---- C = QU @ K^T (64x128), P2 = QV @ R^T (64x192) ----
        {
            int wy = warp & 3, wx = warp >> 2;
            wmma::fragment<wmma::accumulator, 16, 16, 8, float> acc[4];
#pragma unroll
            for (int f = 0; f < 4; f++) wmma::fill_fragment(acc[f], 0.f);
#pragma unroll
            for (int kk = 0; kk < 8; kk++) {
                wmma::fragment<wmma::matrix_a, 16, 16, 8, wmma::precision::tf32, wmma::row_major> af;
                wmma::load_matrix_sync(af, &sQU[(wy * 16) * 68 + kk * 8], 68);
#pragma unroll
                for (int f = 0; f < 4; f++) {
                    wmma::fragment<wmma::matrix_b, 16, 16, 8, wmma::precision::tf32, wmma::col_major> bf;
                    wmma::load_matrix_sync(bf, &sK[(wx * 64 + f * 16) * 68 + kk * 8], 68);
                    wmma::mma_sync(acc[f], af, bf, acc[f]);
                }
            }
#pragma unroll
            for (int f = 0; f < 4; f++)
                wmma::store_matrix_sync(&sC[(wy * 16) * 132 + wx * 64 + f * 16], acc[f], 132,
                                        wmma::mem_row_major);

            wmma::fragment<wmma::accumulator, 16, 16, 8, float> ac2[6];
#pragma unroll
            for (int f = 0; f < 6; f++) wmma::fill_fragment(ac2[f], 0.f);
#pragma unroll
            for (int kk = 0; kk < 8; kk++) {
                wmma::fragment<wmma::matrix_a, 16, 16, 8, wmma::precision::tf32, wmma::row_major> af;
                wmma::load_matrix_sync(af, &sQV[(wy * 16) * 68 + kk * 8], 68);
#pragma unroll
                for (int f = 0; f < 6; f++) {
                    wmma::fragment<wmma::matrix_b, 16, 16, 8, wmma::precision::tf32, wmma::col_major> bf;
                    wmma::load_matrix_sync(bf, &sR[(wx * 96 + f * 16) * 68 + kk * 8], 68);
                    wmma::mma_sync(ac2[f], af, bf, ac2[f]);
                }
            }
#pragma unroll
            for (int f = 0; f < 6; f++)
                wmma::store_matrix_sync(&sP2[(wy * 16) * 196 + wx * 96 + f * 16], ac2[f], 196,
                                        wmma::mem_row_major);
        }
        __syncthreads();

        // ---- load V into sK region; then shift+mask+online softmax ----
        {
            int row = tid >> 1, c0 = (tid & 1) * 32;
            const float* p = V0 + (size_t)(j0 + row) * (BSZ * 2 * DMODEL) + c0;
#pragma unroll
            for (int s = 0; s < 8; s++) {
                float4 v = *reinterpret_cast<const float4*>(p + 4 * s);
                sK[row * 68 + c0 + 4 * s + 0] = wmma::__float_to_tf32(v.x);
                sK[row * 68 + c0 + 4 * s + 1] = wmma::__float_to_tf32(v.y);
                sK[row * 68 + c0 + 4 * s + 2] = wmma::__float_to_tf32(v.z);
                sK[row * 68 + c0 + 4 * s + 3] = wmma::__float_to_tf32(v.w);
            }
        }
        {
            int ri = tid >> 2, q = tid & 3;
            int jmaxl = (i0 + ri) + PREV - j0;       // valid jl <= jmaxl
            int base = q * 32;
            int ush = 63 - ri;
            float v[32];
            float mx = -1e30f;
#pragma unroll
            for (int c = 0; c < 32; c++) {
                int jl = base + c;
                float s = (sC[ri * 132 + jl] + sP2[ri * 196 + jl + ush]) * SCALE;
                if (jl > jmaxl) s = -1e30f;
                v[c] = s;
                mx = fmaxf(mx, s);
            }
            mx = fmaxf(mx, __shfl_xor_sync(0xffffffffu, mx, 1));
            mx = fmaxf(mx, __shfl_xor_sync(0xffffffffu, mx, 2));
            float mprev = sM[ri];
            float mnew = fmaxf(mprev, mx);
            float sum = 0.f;
#pragma unroll
            for (int c = 0; c < 32; c++) {
                float e = __expf(v[c] - mnew);
                sum += e;
                sC[ri * 132 + base + c] = wmma::__float_to_tf32(e);
            }
            sum += __shfl_xor_sync(0xffffffffu, sum, 1);
            sum += __shfl_xor_sync(0xffffffffu, sum, 2);
            if (q == 0) {
                float al = __expf(mprev - mnew);
                sAl[ri] = al;
                sM[ri]  = mnew;
                sL[ri]  = sL[ri] * al + sum;
            }
        }
        __syncthreads();

        // ---- PV = probs(64x128) @ V(128x64) -> sP2 region (64x68) ----
        {
            int wy = warp & 3, wx = warp >> 2;
            wmma::fragment<wmma::accumulator, 16, 16, 8, float> acc[2];
#pragma unroll
            for (int f = 0; f < 2; f++) wmma::fill_fragment(acc[f], 0.f);
#pragma unroll
            for (int kk = 0; kk < 16; kk++) {
                wmma::fragment<wmma::matrix_a, 16, 16, 8, wmma::precision::tf32, wmma::row_major> af;
                wmma::load_matrix_sync(af, &sC[(wy * 16) * 132 + kk * 8], 132);
#pragma unroll
                for (int f = 0; f < 2; f++) {
                    wmma::fragment<wmma::matrix_b, 16, 16, 8, wmma::precision::tf32, wmma::row_major> bf;
                    wmma::load_matrix_sync(bf, &sK[(kk * 8) * 68 + wx * 32 + f * 16], 68);
                    wmma::mma_sync(acc[f], af, bf, acc[f]);
                }
            }
#pragma unroll
            for (int f = 0; f < 2; f++)
                wmma::store_matrix_sync(&sP2[(wy * 16) * 68 + wx * 32 + f * 16], acc[f], 68,
                                        wmma::mem_row_major);
        }
        __syncthreads();

        // ---- merge: O = O * alpha[row] + PV ----
        {
            int ri = tid >> 2, c0 = (tid & 3) * 16;
            float al = sAl[ri];
#pragma unroll
            for (int k = 0; k < 16; k++)
                sO[ri * 68 + c0 + k] = sO[ri * 68 + c0 + k] * al + sP2[ri * 68 + c0 + k];
        }
        __syncthreads();
    }

    // ---- normalize + write ctx ----
    {
        int ri = tid >> 2, c0 = (tid & 3) * 16;
        float inv = 1.f / sL[ri];
        float* op = ctx + (size_t)((i0 + ri) * BSZ + b) * DMODEL + h * HD + c0;
#pragma unroll
        for (int s = 0; s < 4; s++) {
            float4 o;
            o.x = sO[ri * 68 + c0 + 4 * s + 0] * inv;
            o.y = sO[ri * 68 + c0 + 4 * s + 1] * inv;
            o.z = sO[ri * 68 + c0 + 4 * s + 2] * inv;
            o.w = sO[ri * 68 + c0 + 4 * s + 3] * inv;
            *reinterpret_cast<float4*>(op + 4 * s) = o;
        }
    }
}

// ---------------------------------------------------------------------------
// Launch
// ---------------------------------------------------------------------------
extern "C" void kernel_launch(void* const* d_in, const int* in_sizes, int n_in,
                              void* d_out, int out_size)
{
    const float* inputs  = (const float*)d_in[0];
    const float* pos_emb = (const float*)d_in[1];
    const float* full_in = (const float*)d_in[2];
    const float* u       = (const float*)d_in[3];
    const float* v       = (const float*)d_in[4];
    const float* W_kv    = (const float*)d_in[6];
    const float* b_kv    = (const float*)d_in[7];
    const float* W_q     = (const float*)d_in[8];
    const float* b_q     = (const float*)d_in[9];
    const float* W_pos   = (const float*)d_in[10];
    const float* W_proj  = (const float*)d_in[12];
    const float* b_proj  = (const float*)d_in[13];
    float* out = (float*)d_out;

    float *kv, *q, *qu, *qv, *r, *ctx, *beff;
    cudaGetSymbolAddress((void**)&kv,   g_kv);
    cudaGetSymbolAddress((void**)&q,    g_q);
    cudaGetSymbolAddress((void**)&qu,   g_qu);
    cudaGetSymbolAddress((void**)&qv,   g_qv);
    cudaGetSymbolAddress((void**)&r,    g_r);
    cudaGetSymbolAddress((void**)&ctx,  g_ctx);
    cudaGetSymbolAddress((void**)&beff, g_beff);

    static int smem_set = 0;
    if (!smem_set) {
        cudaFuncSetAttribute(flash_kernel, cudaFuncAttributeMaxDynamicSharedMemorySize,
                             SMEM_FLOATS * 4);
        smem_set = 1;
    }

    // Projections (bias-free; biases folded/dropped analytically)
    gemm_tf32<<<dim3(2048 / 128, 8192 / 128), 256>>>(full_in, W_kv, kv, 8192, 2048, 1024);
    gemm_tf32<<<dim3(1024 / 128, 4096 / 128), 256>>>(inputs, W_q, q, 4096, 1024, 1024);
    gemm_tf32<<<dim3(1024 / 128, 2048 / 128), 256>>>(pos_emb, W_pos, r, 2048, 1024, 1024);

    quv_kernel<<<4096, 256>>>(q, b_q, u, v, qu, qv);
    beff_kernel<<<DMODEL / 256, 256>>>(b_kv, W_proj, b_proj, beff);

    // Fused attention (scores + rel_shift + mask + softmax + PV)
    flash_kernel<<<dim3(CUR / IT, ZB), 256, SMEM_FLOATS * 4>>>(qu, qv, kv, r, ctx);

    // out = ctx @ W_proj + b_eff
    gemm_tf32<<<dim3(1024 / 128, 4096 / 128), 256>>>(ctx, W_proj, out, 4096, 1024, 1024);
    bias_add_kernel<<<4096, 256>>>(out, beff);

    (void)in_sizes; (void)n_in; (void)out_size;
}

// round 5
// speedup vs baseline: 1.1404x; 1.1404x over previous
#include <cuda_runtime.h>
#include <cuda_bf16.h>
#include <mma.h>
#include <cstdint>

using namespace nvcuda;

// Problem constants
#define CUR    1024
#define FULL   2048
#define BSZ    4
#define DMODEL 1024
#define HN     16
#define HD     64
#define PREV   (FULL - CUR)      // 1024
#define ZB     (BSZ * HN)        // 64 batched heads
#define SCALE  0.125f            // 1/sqrt(64)

// ---------------------------------------------------------------------------
// Scratch
// ---------------------------------------------------------------------------
__device__ float g_kv [ (size_t)FULL * BSZ * 2 * HN * HD ];   // 8192 x 2048
__device__ float g_q  [ (size_t)CUR * BSZ * HN * HD ];        // 4096 x 1024
__device__ float g_qu [ (size_t)CUR * BSZ * HN * HD ];
__device__ float g_qv [ (size_t)CUR * BSZ * HN * HD ];
__device__ float g_r  [ (size_t)FULL * HN * HD ];             // 2048 x 1024
__device__ float g_ctx[ (size_t)CUR * BSZ * HN * HD ];
__device__ float g_scores[ (size_t)ZB * CUR * FULL ];         // content -> probs
__device__ float g_pos   [ (size_t)ZB * CUR * FULL ];         // unshifted position
__device__ float g_beff[ DMODEL ];

#define TF32(x) wmma::__float_to_tf32(x)

// ---------------------------------------------------------------------------
// TF32 GEMM with 2-stage register prefetch: C[M,N] = A[M,K] @ B[K,N]
// 128x128 tile, KC=32, 256 threads, 8 warps each 64x32.
// ---------------------------------------------------------------------------
__global__ __launch_bounds__(256) void gemm_tf32(
    const float* __restrict__ A, const float* __restrict__ B,
    float* __restrict__ C, int M, int N, int K)
{
    __shared__ float sA[128][40];   // [m][k]
    __shared__ float sB[32][136];   // [k][n]
    int tid = threadIdx.x, warp = tid >> 5;
    int wm = warp >> 2, wn = warp & 3;
    int m0 = blockIdx.y * 128, n0 = blockIdx.x * 128;

    wmma::fragment<wmma::accumulator, 16, 16, 8, float> acc[4][2];
#pragma unroll
    for (int i = 0; i < 4; i++)
#pragma unroll
        for (int j = 0; j < 2; j++) wmma::fill_fragment(acc[i][j], 0.f);

    int am = tid >> 1,  ak = (tid & 1) * 16;
    int bk = tid >> 3,  bn = (tid & 7) * 16;

    const float* Abase = A + (size_t)(m0 + am) * K + ak;
    const float* Bbase = B + (size_t)bk * N + n0 + bn;

    float4 pa[4], pb[4];
#pragma unroll
    for (int s = 0; s < 4; s++) {
        pa[s] = *reinterpret_cast<const float4*>(Abase + 4 * s);
        pb[s] = *reinterpret_cast<const float4*>(Bbase + 4 * s);
    }

    for (int k0 = 0; k0 < K; k0 += 32) {
        // commit prefetched regs -> smem (with tf32 rounding)
#pragma unroll
        for (int s = 0; s < 4; s++) {
            sA[am][ak + 4 * s + 0] = TF32(pa[s].x);
            sA[am][ak + 4 * s + 1] = TF32(pa[s].y);
            sA[am][ak + 4 * s + 2] = TF32(pa[s].z);
            sA[am][ak + 4 * s + 3] = TF32(pa[s].w);
            sB[bk][bn + 4 * s + 0] = TF32(pb[s].x);
            sB[bk][bn + 4 * s + 1] = TF32(pb[s].y);
            sB[bk][bn + 4 * s + 2] = TF32(pb[s].z);
            sB[bk][bn + 4 * s + 3] = TF32(pb[s].w);
        }
        __syncthreads();

        // prefetch next K-chunk while MMAs run
        int kn = k0 + 32;
        if (kn < K) {
            const float* ap = Abase + kn;
            const float* bp = Bbase + (size_t)kn * N;
#pragma unroll
            for (int s = 0; s < 4; s++) {
                pa[s] = *reinterpret_cast<const float4*>(ap + 4 * s);
                pb[s] = *reinterpret_cast<const float4*>(bp + 4 * s);
            }
        }

#pragma unroll
        for (int kk = 0; kk < 4; kk++) {
            wmma::fragment<wmma::matrix_a, 16, 16, 8, wmma::precision::tf32, wmma::row_major> af[4];
            wmma::fragment<wmma::matrix_b, 16, 16, 8, wmma::precision::tf32, wmma::row_major> bf[2];
#pragma unroll
            for (int i = 0; i < 4; i++)
                wmma::load_matrix_sync(af[i], &sA[wm * 64 + i * 16][kk * 8], 40);
#pragma unroll
            for (int j = 0; j < 2; j++)
                wmma::load_matrix_sync(bf[j], &sB[kk * 8][wn * 32 + j * 16], 136);
#pragma unroll
            for (int i = 0; i < 4; i++)
#pragma unroll
                for (int j = 0; j < 2; j++)
                    wmma::mma_sync(acc[i][j], af[i], bf[j], acc[i][j]);
        }
        __syncthreads();
    }
#pragma unroll
    for (int i = 0; i < 4; i++)
#pragma unroll
        for (int j = 0; j < 2; j++)
            wmma::store_matrix_sync(
                C + (size_t)(m0 + wm * 64 + i * 16) * N + n0 + wn * 32 + j * 16,
                acc[i][j], N, wmma::mem_row_major);
}

// ---------------------------------------------------------------------------
// qu = q + (b_q + u)[n],  qv = q + (b_q + v)[n]
// ---------------------------------------------------------------------------
__global__ __launch_bounds__(256) void quv_kernel(
    const float* __restrict__ q, const float* __restrict__ b_q,
    const float* __restrict__ u, const float* __restrict__ v,
    float* __restrict__ qu, float* __restrict__ qv)
{
    int idx = blockIdx.x * 256 + threadIdx.x;
    int n4 = idx & 255;
    float4 qq = reinterpret_cast<const float4*>(q)[idx];
    float4 bb = reinterpret_cast<const float4*>(b_q)[n4];
    float4 uu = reinterpret_cast<const float4*>(u)[n4];
    float4 vv = reinterpret_cast<const float4*>(v)[n4];
    float4 a, c;
    a.x = qq.x + bb.x + uu.x; a.y = qq.y + bb.y + uu.y;
    a.z = qq.z + bb.z + uu.z; a.w = qq.w + bb.w + uu.w;
    c.x = qq.x + bb.x + vv.x; c.y = qq.y + bb.y + vv.y;
    c.z = qq.z + bb.z + vv.z; c.w = qq.w + bb.w + vv.w;
    reinterpret_cast<float4*>(qu)[idx] = a;
    reinterpret_cast<float4*>(qv)[idx] = c;
}

__global__ __launch_bounds__(256) void beff_kernel(
    const float* __restrict__ b_kv, const float* __restrict__ W_proj,
    const float* __restrict__ b_proj, float* __restrict__ beff)
{
    int n = blockIdx.x * 256 + threadIdx.x;
    float acc = b_proj[n];
    for (int m = 0; m < DMODEL; m++)
        acc += b_kv[DMODEL + m] * W_proj[(size_t)m * DMODEL + n];
    beff[n] = acc;
}

__global__ __launch_bounds__(256) void bias_add_kernel(
    float* __restrict__ out, const float* __restrict__ beff)
{
    int idx = blockIdx.x * 256 + threadIdx.x;
    int n4 = idx & 255;
    float4 o = reinterpret_cast<float4*>(out)[idx];
    float4 b = reinterpret_cast<const float4*>(beff)[n4];
    o.x += b.x; o.y += b.y; o.z += b.z; o.w += b.w;
    reinterpret_cast<float4*>(out)[idx] = o;
}

// ---------------------------------------------------------------------------
// Score GEMM (content or unshifted position), TF32 (as R2):
//   OUT[z,i,j] = sum_d A(i,d) * B(j,d)
// 128x128 tile, K=64 in 2 chunks of 32; analytic block skips.
// ---------------------------------------------------------------------------
__global__ __launch_bounds__(256) void score_tf32(
    const float* __restrict__ QU, const float* __restrict__ SRC,
    float* __restrict__ OUT, int isPos)
{
    int i0 = blockIdx.y * 128, j0 = blockIdx.x * 128;
    if (!isPos && j0 >= i0 + 1152) return;                 // all masked
    if (isPos && (i0 + j0 + 254) < 1023) return;           // never read after shift
    int z = blockIdx.z;
    int b = z >> 4, h = z & 15;
    const float* A0 = QU + b * DMODEL + h * HD;            // ld 4096
    const float* B0 = isPos ? (SRC + h * HD) : (SRC + b * 2048 + h * HD);
    size_t ldB = isPos ? (size_t)(HN * HD) : (size_t)(BSZ * 2 * HN * HD);

    __shared__ float sA[128][40];
    __shared__ float sB[128][40];
    int tid = threadIdx.x, warp = tid >> 5;
    int wm = warp >> 2, wn = warp & 3;

    wmma::fragment<wmma::accumulator, 16, 16, 8, float> acc[4][2];
#pragma unroll
    for (int i = 0; i < 4; i++)
#pragma unroll
        for (int j = 0; j < 2; j++) wmma::fill_fragment(acc[i][j], 0.f);

    int rm = tid >> 1, rk = (tid & 1) * 16;

    const float* Abase = A0 + (size_t)(i0 + rm) * (BSZ * DMODEL) + rk;
    const float* Bbase = B0 + (size_t)(j0 + rm) * ldB + rk;

    float4 pa[4], pb[4];
#pragma unroll
    for (int s = 0; s < 4; s++) {
        pa[s] = *reinterpret_cast<const float4*>(Abase + 4 * s);
        pb[s] = *reinterpret_cast<const float4*>(Bbase + 4 * s);
    }

    for (int d0 = 0; d0 < HD; d0 += 32) {
#pragma unroll
        for (int s = 0; s < 4; s++) {
            sA[rm][rk + 4 * s + 0] = TF32(pa[s].x);
            sA[rm][rk + 4 * s + 1] = TF32(pa[s].y);
            sA[rm][rk + 4 * s + 2] = TF32(pa[s].z);
            sA[rm][rk + 4 * s + 3] = TF32(pa[s].w);
            sB[rm][rk + 4 * s + 0] = TF32(pb[s].x);
            sB[rm][rk + 4 * s + 1] = TF32(pb[s].y);
            sB[rm][rk + 4 * s + 2] = TF32(pb[s].z);
            sB[rm][rk + 4 * s + 3] = TF32(pb[s].w);
        }
        __syncthreads();
        if (d0 + 32 < HD) {
#pragma unroll
            for (int s = 0; s < 4; s++) {
                pa[s] = *reinterpret_cast<const float4*>(Abase + 32 + 4 * s);
                pb[s] = *reinterpret_cast<const float4*>(Bbase + 32 + 4 * s);
            }
        }
#pragma unroll
        for (int kk = 0; kk < 4; kk++) {
            wmma::fragment<wmma::matrix_a, 16, 16, 8, wmma::precision::tf32, wmma::row_major> af[4];
            wmma::fragment<wmma::matrix_b, 16, 16, 8, wmma::precision::tf32, wmma::col_major> bf[2];
#pragma unroll
            for (int i = 0; i < 4; i++)
                wmma::load_matrix_sync(af[i], &sA[wm * 64 + i * 16][kk * 8], 40);
#pragma unroll
            for (int j = 0; j < 2; j++)
                wmma::load_matrix_sync(bf[j], &sB[wn * 32 + j * 16][kk * 8], 40);
#pragma unroll
            for (int i = 0; i < 4; i++)
#pragma unroll
                for (int j = 0; j < 2; j++)
                    wmma::mma_sync(acc[i][j], af[i], bf[j], acc[i][j]);
        }
        __syncthreads();
    }
    float* C0 = OUT + (size_t)z * CUR * FULL;
#pragma unroll
    for (int i = 0; i < 4; i++)
#pragma unroll
        for (int j = 0; j < 2; j++)
            wmma::store_matrix_sync(
                C0 + (size_t)(i0 + wm * 64 + i * 16) * FULL + j0 + wn * 32 + j * 16,
                acc[i][j], FULL, wmma::mem_row_major);
}

// ---------------------------------------------------------------------------
// Fused rel_shift gather + mask + softmax (in place into g_scores).
// ---------------------------------------------------------------------------
__global__ __launch_bounds__(256) void softmax_kernel(
    const float* __restrict__ cont, const float* __restrict__ pos,
    float* __restrict__ out)
{
    int i = blockIdx.x;
    int z = blockIdx.y;
    int tid = threadIdx.x;
    size_t rowOff = ((size_t)z * CUR + i) * FULL;
    const float* c = cont + rowOff;
    const float* p = pos + rowOff;
    int jmax  = i + PREV;
    int shift = CUR - 1 - i;

    float vals[8];
    float mx = -1e30f;
#pragma unroll
    for (int it = 0; it < 8; it++) {
        int j = tid + it * 256;
        float s = -1e30f;
        if (j <= jmax) s = (c[j] + p[j + shift]) * SCALE;
        vals[it] = s;
        mx = fmaxf(mx, s);
    }
    __shared__ float redm[8];
    __shared__ float reds[8];
#pragma unroll
    for (int o = 16; o; o >>= 1) mx = fmaxf(mx, __shfl_xor_sync(0xffffffffu, mx, o));
    if ((tid & 31) == 0) redm[tid >> 5] = mx;
    __syncthreads();
    mx = redm[0];
#pragma unroll
    for (int w = 1; w < 8; w++) mx = fmaxf(mx, redm[w]);

    float sum = 0.f;
#pragma unroll
    for (int it = 0; it < 8; it++) {
        float e = __expf(vals[it] - mx);
        vals[it] = e;
        sum += e;
    }
#pragma unroll
    for (int o = 16; o; o >>= 1) sum += __shfl_xor_sync(0xffffffffu, sum, o);
    if ((tid & 31) == 0) reds[tid >> 5] = sum;
    __syncthreads();
    sum = 0.f;
#pragma unroll
    for (int w = 0; w < 8; w++) sum += reds[w];
    float inv = 1.f / sum;

    float* o = out + rowOff;
#pragma unroll
    for (int it = 0; it < 8; it++) {
        int j = tid + it * 256;
        o[j] = (j <= jmax) ? vals[it] * inv : 0.f;
    }
}

// ---------------------------------------------------------------------------
// Context GEMM, TF32 with register prefetch:
//   ctx[(i*BSZ+b)*1024 + h*64 + d] = sum_j P[z,i,j] val(j,d)
// Block 128(i) x 64(d); K truncated at i0+1152.
// ---------------------------------------------------------------------------
__global__ __launch_bounds__(256) void ctx_tf32(
    const float* __restrict__ probs, const float* __restrict__ kv,
    float* __restrict__ ctx)
{
    int z = blockIdx.y;
    int b = z >> 4, h = z & 15;
    int i0 = blockIdx.x * 128;
    const float* A0 = probs + (size_t)z * CUR * FULL;
    const float* B0 = kv + (size_t)b * 2048 + HN * HD + h * HD;

    __shared__ float sA[128][40];
    __shared__ float sB[32][72];
    int tid = threadIdx.x, warp = tid >> 5;
    int wm = warp >> 1, wn = warp & 1;

    wmma::fragment<wmma::accumulator, 16, 16, 8, float> acc[2][2];
#pragma unroll
    for (int i = 0; i < 2; i++)
#pragma unroll
        for (int j = 0; j < 2; j++) wmma::fill_fragment(acc[i][j], 0.f);

    int am = tid >> 1, aj = (tid & 1) * 16;
    int bj = tid >> 3, bd = (tid & 7) * 8;

    int kmax = i0 + 1152;  if (kmax > FULL) kmax = FULL;

    const float* Abase = A0 + (size_t)(i0 + am) * FULL + aj;
    const float* Bbase = B0 + (size_t)bj * (BSZ * 2 * HN * HD) + bd;
    const size_t bstr = (size_t)(BSZ * 2 * HN * HD);

    float4 pa[4], pb[2];
#pragma unroll
    for (int s = 0; s < 4; s++) pa[s] = *reinterpret_cast<const float4*>(Abase + 4 * s);
#pragma unroll
    for (int s = 0; s < 2; s++) pb[s] = *reinterpret_cast<const float4*>(Bbase + 4 * s);

    for (int k0 = 0; k0 < kmax; k0 += 32) {
#pragma unroll
        for (int s = 0; s < 4; s++) {
            sA[am][aj + 4 * s + 0] = TF32(pa[s].x);
            sA[am][aj + 4 * s + 1] = TF32(pa[s].y);
            sA[am][aj + 4 * s + 2] = TF32(pa[s].z);
            sA[am][aj + 4 * s + 3] = TF32(pa[s].w);
        }
#pragma unroll
        for (int s = 0; s < 2; s++) {
            sB[bj][bd + 4 * s + 0] = TF32(pb[s].x);
            sB[bj][bd + 4 * s + 1] = TF32(pb[s].y);
            sB[bj][bd + 4 * s + 2] = TF32(pb[s].z);
            sB[bj][bd + 4 * s + 3] = TF32(pb[s].w);
        }
        __syncthreads();

        int kn = k0 + 32;
        if (kn < kmax) {
            const float* ap = Abase + kn;
            const float* bp = Bbase + (size_t)kn * bstr;
#pragma unroll
            for (int s = 0; s < 4; s++) pa[s] = *reinterpret_cast<const float4*>(ap + 4 * s);
#pragma unroll
            for (int s = 0; s < 2; s++) pb[s] = *reinterpret_cast<const float4*>(bp + 4 * s);
        }

#pragma unroll
        for (int kk = 0; kk < 4; kk++) {
            wmma::fragment<wmma::matrix_a, 16, 16, 8, wmma::precision::tf32, wmma::row_major> af[2];
            wmma::fragment<wmma::matrix_b, 16, 16, 8, wmma::precision::tf32, wmma::row_major> bf[2];
#pragma unroll
            for (int i = 0; i < 2; i++)
                wmma::load_matrix_sync(af[i], &sA[wm * 32 + i * 16][kk * 8], 40);
#pragma unroll
            for (int j = 0; j < 2; j++)
                wmma::load_matrix_sync(bf[j], &sB[kk * 8][wn * 32 + j * 16], 72);
#pragma unroll
            for (int i = 0; i < 2; i++)
#pragma unroll
                for (int j = 0; j < 2; j++)
                    wmma::mma_sync(acc[i][j], af[i], bf[j], acc[i][j]);
        }
        __syncthreads();
    }
#pragma unroll
    for (int i = 0; i < 2; i++)
#pragma unroll
        for (int j = 0; j < 2; j++)
            wmma::store_matrix_sync(
                ctx + (size_t)((i0 + wm * 32 + i * 16) * BSZ + b) * DMODEL + h * HD + wn * 32 + j * 16,
                acc[i][j], BSZ * DMODEL, wmma::mem_row_major);
}

// ---------------------------------------------------------------------------
// Launch
// ---------------------------------------------------------------------------
extern "C" void kernel_launch(void* const* d_in, const int* in_sizes, int n_in,
                              void* d_out, int out_size)
{
    const float* inputs  = (const float*)d_in[0];
    const float* pos_emb = (const float*)d_in[1];
    const float* full_in = (const float*)d_in[2];
    const float* u       = (const float*)d_in[3];
    const float* v       = (const float*)d_in[4];
    const float* W_kv    = (const float*)d_in[6];
    const float* b_kv    = (const float*)d_in[7];
    const float* W_q     = (const float*)d_in[8];
    const float* b_q     = (const float*)d_in[9];
    const float* W_pos   = (const float*)d_in[10];
    const float* W_proj  = (const float*)d_in[12];
    const float* b_proj  = (const float*)d_in[13];
    float* out = (float*)d_out;

    float *kv, *q, *qu, *qv, *r, *ctx, *scores, *pos, *beff;
    cudaGetSymbolAddress((void**)&kv,     g_kv);
    cudaGetSymbolAddress((void**)&q,      g_q);
    cudaGetSymbolAddress((void**)&qu,     g_qu);
    cudaGetSymbolAddress((void**)&qv,     g_qv);
    cudaGetSymbolAddress((void**)&r,      g_r);
    cudaGetSymbolAddress((void**)&ctx,    g_ctx);
    cudaGetSymbolAddress((void**)&scores, g_scores);
    cudaGetSymbolAddress((void**)&pos,    g_pos);
    cudaGetSymbolAddress((void**)&beff,   g_beff);

    // Projections (bias-free; biases folded/dropped analytically)
    gemm_tf32<<<dim3(2048 / 128, 8192 / 128), 256>>>(full_in, W_kv, kv, 8192, 2048, 1024);
    gemm_tf32<<<dim3(1024 / 128, 4096 / 128), 256>>>(inputs, W_q, q, 4096, 1024, 1024);
    gemm_tf32<<<dim3(1024 / 128, 2048 / 128), 256>>>(pos_emb, W_pos, r, 2048, 1024, 1024);

    quv_kernel<<<4096, 256>>>(q, b_q, u, v, qu, qv);
    beff_kernel<<<DMODEL / 256, 256>>>(b_kv, W_proj, b_proj, beff);

    // Scores on tensor pipe
    score_tf32<<<dim3(FULL / 128, CUR / 128, ZB), 256>>>(qu, kv, scores, 0);
    score_tf32<<<dim3(FULL / 128, CUR / 128, ZB), 256>>>(qv, r, pos, 1);

    // shift + mask + softmax (in place)
    softmax_kernel<<<dim3(CUR, ZB), 256>>>(scores, pos, scores);

    // ctx = probs @ val
    ctx_tf32<<<dim3(CUR / 128, ZB), 256>>>(scores, kv, ctx);

    // out = ctx @ W_proj + b_eff
    gemm_tf32<<<dim3(1024 / 128, 4096 / 128), 256>>>(ctx, W_proj, out, 4096, 1024, 1024);
    bias_add_kernel<<<4096, 256>>>(out, beff);

    (void)in_sizes; (void)n_in; (void)out_size;
}